// round 3
// baseline (speedup 1.0000x reference)
#include <cuda_runtime.h>
#include <cstdint>

// out[i] = W[inputs[i] - 1];  N = 16384*200 = 3,276,800 elems;  W: 200 floats.
// Index dtype probe: idx_raw[1] == 0 -> int64 (high word of elem 0),
//                    != 0            -> int32 (elem 1, in [1,200]).

#define N_TOTAL   (16384 * 200)
#define N_UNITS   (N_TOTAL / 4)          // 819,200 float4 output units
#define MAX_RANKS 200
#define TPB       512
#define NCTAS     592                    // 148 SMs * 4
#define S_THREADS ((long long)NCTAS * TPB)   // 303,104; 3*S >= N_UNITS

__global__ __launch_bounds__(TPB)
void bias_gather_kernel(const uint32_t* __restrict__ idx_raw,
                        const float* __restrict__ W,
                        float* __restrict__ out)
{
    // 32-way replicated W: sW[rank*32 + lane] -> bank == lane, conflict-free.
    __shared__ float sW[MAX_RANKS * 32];

    const int tid  = threadIdx.x;
    const int lane = tid & 31;
    const int wid  = tid >> 5;

    const long long g  = (long long)blockIdx.x * TPB + tid;
    const bool has2 = (g + 2 * S_THREADS) < N_UNITS;

    // ---- Front-batch ALL global loads (probe + indices) before the fill ----
    const uint32_t probe = idx_raw[1];
    const bool is64 = (probe == 0u);

    // Raw 16-byte chunks of index data. int64: 2 chunks/unit; int32: 1 chunk/unit.
    uint4 c0, c1, c2, c3, c4, c5;
    const uint4* __restrict__ p = reinterpret_cast<const uint4*>(idx_raw);

    if (is64) {
        c0 = p[2 * g];                       // unit0
        c1 = p[2 * g + 1];
        c2 = p[2 * (g + S_THREADS)];         // unit1
        c3 = p[2 * (g + S_THREADS) + 1];
        if (has2) {
            c4 = p[2 * (g + 2 * S_THREADS)]; // unit2
            c5 = p[2 * (g + 2 * S_THREADS) + 1];
        }
    } else {
        c0 = p[g];                           // unit0
        c1 = p[g + S_THREADS];               // unit1
        if (has2) c2 = p[g + 2 * S_THREADS]; // unit2
    }

    // ---- Fill replicated W while index loads are in flight ----
    #pragma unroll
    for (int k = wid; k < MAX_RANKS; k += TPB / 32) {
        float v = W[k];             // warp-uniform addr: single sector
        sW[k * 32 + lane] = v;      // conflict-free STS
    }
    __syncthreads();

    // ---- Gather (conflict-free LDS) + coalesced float4 stores ----
    float4* __restrict__ out4 = reinterpret_cast<float4*>(out);

    float4 r0, r1, r2;
    if (is64) {
        // little-endian int64: low words at .x and .z of each 16B chunk
        r0.x = sW[((int)c0.x - 1) * 32 + lane];
        r0.y = sW[((int)c0.z - 1) * 32 + lane];
        r0.z = sW[((int)c1.x - 1) * 32 + lane];
        r0.w = sW[((int)c1.z - 1) * 32 + lane];

        r1.x = sW[((int)c2.x - 1) * 32 + lane];
        r1.y = sW[((int)c2.z - 1) * 32 + lane];
        r1.z = sW[((int)c3.x - 1) * 32 + lane];
        r1.w = sW[((int)c3.z - 1) * 32 + lane];

        if (has2) {
            r2.x = sW[((int)c4.x - 1) * 32 + lane];
            r2.y = sW[((int)c4.z - 1) * 32 + lane];
            r2.z = sW[((int)c5.x - 1) * 32 + lane];
            r2.w = sW[((int)c5.z - 1) * 32 + lane];
        }
    } else {
        r0.x = sW[((int)c0.x - 1) * 32 + lane];
        r0.y = sW[((int)c0.y - 1) * 32 + lane];
        r0.z = sW[((int)c0.z - 1) * 32 + lane];
        r0.w = sW[((int)c0.w - 1) * 32 + lane];

        r1.x = sW[((int)c1.x - 1) * 32 + lane];
        r1.y = sW[((int)c1.y - 1) * 32 + lane];
        r1.z = sW[((int)c1.z - 1) * 32 + lane];
        r1.w = sW[((int)c1.w - 1) * 32 + lane];

        if (has2) {
            r2.x = sW[((int)c2.x - 1) * 32 + lane];
            r2.y = sW[((int)c2.y - 1) * 32 + lane];
            r2.z = sW[((int)c2.z - 1) * 32 + lane];
            r2.w = sW[((int)c2.w - 1) * 32 + lane];
        }
    }

    out4[g] = r0;
    out4[g + S_THREADS] = r1;
    if (has2) out4[g + 2 * S_THREADS] = r2;
}

extern "C" void kernel_launch(void* const* d_in, const int* in_sizes, int n_in,
                              void* d_out, int out_size)
{
    const uint32_t* idx = (const uint32_t*)d_in[0];  // inputs [16384, 200]
    const float*    W   = (const float*)d_in[1];     // [200, 1]
    float*          out = (float*)d_out;

    bias_gather_kernel<<<NCTAS, TPB>>>(idx, W, out);
}

// round 4
// speedup vs baseline: 1.0036x; 1.0036x over previous
#include <cuda_runtime.h>
#include <cstdint>

// out[i] = W[inputs[i] - 1];  N = 16384*200 = 3,276,800;  W: 200 floats.
// Index dtype probe: idx_raw[1]==0 -> int64 (high word of elem 0), else int32.
//
// Model: kernel is LTS-byte bound. Mandatory traffic = 26.2MB idx read +
// 13.1MB out write. Avoid the extra 13.1MB dirty-eviction pass by writing
// the output with st.global.wt (no L2 allocate, single LTS crossing).

#define N_TOTAL   (16384 * 200)
#define N_UNITS   (N_TOTAL / 4)      // 819,200 float4 output units
#define MAX_RANKS 200
#define TPB       512
#define NCTAS     (148 * 4)          // one full wave, 64 warps/SM

__global__ __launch_bounds__(TPB)
void bias_gather_kernel(const uint32_t* __restrict__ idx_raw,
                        const float* __restrict__ W,
                        float* __restrict__ out)
{
    // 32-way replicated W: sW[rank*32 + lane] -> bank == lane, conflict-free.
    __shared__ float sW[MAX_RANKS * 32];

    const int tid  = threadIdx.x;
    const int lane = tid & 31;
    const int wid  = tid >> 5;

    // Probe dtype early; keep indices L2-cached (default policy) for replays.
    const uint32_t probe = __ldcg(idx_raw + 1);

    #pragma unroll
    for (int k = wid; k < MAX_RANKS; k += TPB / 32) {
        float v = W[k];                 // warp-uniform addr: 1 sector
        sW[k * 32 + lane] = v;          // conflict-free STS
    }
    __syncthreads();

    const long long g      = (long long)blockIdx.x * TPB + tid;
    const long long stride = (long long)gridDim.x * TPB;
    float4* __restrict__ out4 = reinterpret_cast<float4*>(out);

    if (probe == 0u) {
        // int64 indices: 4 idx = two 16B loads (low words at .x/.z)
        const uint4* __restrict__ p = reinterpret_cast<const uint4*>(idx_raw);
        for (long long u = g; u < N_UNITS; u += stride) {
            uint4 a = __ldcg(p + 2 * u);
            uint4 b = __ldcg(p + 2 * u + 1);
            float4 r;
            r.x = sW[((int)a.x - 1) * 32 + lane];
            r.y = sW[((int)a.z - 1) * 32 + lane];
            r.z = sW[((int)b.x - 1) * 32 + lane];
            r.w = sW[((int)b.z - 1) * 32 + lane];
            __stwt(out4 + u, r);        // write-through: no L2 allocate/evict
        }
    } else {
        // int32 indices: 4 idx = one 16B load
        const uint4* __restrict__ p = reinterpret_cast<const uint4*>(idx_raw);
        for (long long u = g; u < N_UNITS; u += stride) {
            uint4 a = __ldcg(p + u);
            float4 r;
            r.x = sW[((int)a.x - 1) * 32 + lane];
            r.y = sW[((int)a.y - 1) * 32 + lane];
            r.z = sW[((int)a.z - 1) * 32 + lane];
            r.w = sW[((int)a.w - 1) * 32 + lane];
            __stwt(out4 + u, r);
        }
    }
}

extern "C" void kernel_launch(void* const* d_in, const int* in_sizes, int n_in,
                              void* d_out, int out_size)
{
    const uint32_t* idx = (const uint32_t*)d_in[0];  // inputs [16384, 200]
    const float*    W   = (const float*)d_in[1];     // [200, 1]
    float*          out = (float*)d_out;

    bias_gather_kernel<<<NCTAS, TPB>>>(idx, W, out);
}